// round 12
// baseline (speedup 1.0000x reference)
#include <cuda_runtime.h>
#include <cuda_bf16.h>
#include <math.h>
#include <stdint.h>

// ----------------------------------------------------------------------------
// Problem constants
// ----------------------------------------------------------------------------
#define D_MODEL   2048
#define NUM_HEADS 16
#define D_K       128
#define HALF_DK   64
#define BATCH     2
#define SEQ       2048
#define M_ROWS    (BATCH * SEQ)
#define NX (M_ROWS * D_MODEL)
#define NW (D_MODEL * D_MODEL)

typedef __nv_bfloat16  bf16;
typedef __nv_bfloat162 bf162;

// ----------------------------------------------------------------------------
// Scratch (device globals; hi at [0,N), lo at [N,2N)). Device-code refs only.
// ----------------------------------------------------------------------------
__device__ float g_Qf[NX];
__device__ float g_Kf[NX];

__device__ bf16 g_x [2 * NX];
__device__ bf16 g_Wq[2 * NW], g_Wk[2 * NW], g_Wv[2 * NW], g_Wo[2 * NW];
__device__ bf16 g_Q [2 * NX], g_K [2 * NX], g_V [2 * NX], g_ctx[2 * NX];
__device__ float2 g_rope[M_ROWS * HALF_DK];   // (cos, sin) per (row, pair)

// ----------------------------------------------------------------------------
// PTX helpers
// ----------------------------------------------------------------------------
__device__ __forceinline__ void ldsm_x4(uint32_t* r, uint32_t addr) {
    asm volatile("ldmatrix.sync.aligned.m8n8.x4.shared.b16 {%0,%1,%2,%3}, [%4];"
                 : "=r"(r[0]), "=r"(r[1]), "=r"(r[2]), "=r"(r[3]) : "r"(addr));
}
__device__ __forceinline__ void ldsm_x4_t(uint32_t* r, uint32_t addr) {
    asm volatile("ldmatrix.sync.aligned.m8n8.x4.trans.shared.b16 {%0,%1,%2,%3}, [%4];"
                 : "=r"(r[0]), "=r"(r[1]), "=r"(r[2]), "=r"(r[3]) : "r"(addr));
}
__device__ __forceinline__ void mma16816(float* c, const uint32_t* a, const uint32_t* b) {
    asm volatile("mma.sync.aligned.m16n8k16.row.col.f32.bf16.bf16.f32 "
                 "{%0,%1,%2,%3},{%4,%5,%6,%7},{%8,%9},{%0,%1,%2,%3};"
                 : "+f"(c[0]), "+f"(c[1]), "+f"(c[2]), "+f"(c[3])
                 : "r"(a[0]), "r"(a[1]), "r"(a[2]), "r"(a[3]), "r"(b[0]), "r"(b[1]));
}
__device__ __forceinline__ void cp16a(uint32_t dst, const void* src) {
    asm volatile("cp.async.ca.shared.global [%0], [%1], 16;" :: "r"(dst), "l"(src));
}
__device__ __forceinline__ void cp_commit() { asm volatile("cp.async.commit_group;"); }
__device__ __forceinline__ void cp_wait1()  { asm volatile("cp.async.wait_group 1;"); }
__device__ __forceinline__ void cp_wait0()  { asm volatile("cp.async.wait_group 0;"); }

// ----------------------------------------------------------------------------
// Split all 5 inputs fp32 -> (hi, lo) bf16. Dest selected in device code.
// ----------------------------------------------------------------------------
__global__ void split_all(const float* __restrict__ x,
                          const float* __restrict__ Wq,
                          const float* __restrict__ Wk,
                          const float* __restrict__ Wv,
                          const float* __restrict__ Wo)
{
    const float* src;
    bf16 *h, *l;
    int n4;
    switch (blockIdx.y) {
        case 0:  src = x;  h = g_x;  l = g_x  + NX; n4 = NX / 4; break;
        case 1:  src = Wq; h = g_Wq; l = g_Wq + NW; n4 = NW / 4; break;
        case 2:  src = Wk; h = g_Wk; l = g_Wk + NW; n4 = NW / 4; break;
        case 3:  src = Wv; h = g_Wv; l = g_Wv + NW; n4 = NW / 4; break;
        default: src = Wo; h = g_Wo; l = g_Wo + NW; n4 = NW / 4; break;
    }
    int i = blockIdx.x * blockDim.x + threadIdx.x;
    if (i >= n4) return;
    float4 v = ((const float4*)src)[i];
    float vv[4] = {v.x, v.y, v.z, v.w};
    bf16 hh[4], ll[4];
#pragma unroll
    for (int e = 0; e < 4; e++) {
        hh[e] = __float2bfloat16(vv[e]);
        ll[e] = __float2bfloat16(vv[e] - __bfloat162float(hh[e]));
    }
    ((bf162*)h)[i * 2]     = bf162(hh[0], hh[1]);
    ((bf162*)h)[i * 2 + 1] = bf162(hh[2], hh[3]);
    ((bf162*)l)[i * 2]     = bf162(ll[0], ll[1]);
    ((bf162*)l)[i * 2 + 1] = bf162(ll[2], ll[3]);
}

// ----------------------------------------------------------------------------
// RoPE phase 1: cos/sin table, fp64 angles, one entry per (row, pair).
// 262K threads instead of 4.2M fp64-transcendental threads.
// ----------------------------------------------------------------------------
__global__ void rope_table_kernel(const int* __restrict__ pos)
{
    int idx = blockIdx.x * blockDim.x + threadIdx.x;
    if (idx >= M_ROWS * HALF_DK) return;
    int i = idx % HALF_DK;
    int m = idx / HALF_DK;
    double ang = (double)pos[m] * pow(10000.0, -(double)i / 64.0);
    g_rope[idx] = make_float2((float)cos(ang), (float)sin(ang));
}

// ----------------------------------------------------------------------------
// RoPE phase 2: apply rotation (fp32) + hi/lo split; Q pre-scaled by 1/sqrt(dk).
// ----------------------------------------------------------------------------
__global__ void rope_split_kernel()
{
    int idx = blockIdx.x * blockDim.x + threadIdx.x;
    const int total = M_ROWS * NUM_HEADS * HALF_DK;
    if (idx >= total) return;

    int i = idx % HALF_DK;
    int h = (idx / HALF_DK) % NUM_HEADS;
    int m = idx / (HALF_DK * NUM_HEADS);

    float2 cs = g_rope[m * HALF_DK + i];
    float c = cs.x, s = cs.y;
    const float qscale = 0.08838834764831845f;

    size_t base = (size_t)m * D_MODEL + h * D_K + 2 * i;

    float q1 = g_Qf[base], q2 = g_Qf[base + 1];
    float qr1 = (q1 * c - q2 * s) * qscale;
    float qr2 = (q1 * s + q2 * c) * qscale;
    bf162 qh = __floats2bfloat162_rn(qr1, qr2);
    bf162 ql = __floats2bfloat162_rn(qr1 - __bfloat162float(qh.x),
                                     qr2 - __bfloat162float(qh.y));
    *(bf162*)&g_Q[base]      = qh;
    *(bf162*)&g_Q[NX + base] = ql;

    float k1 = g_Kf[base], k2 = g_Kf[base + 1];
    float kr1 = k1 * c - k2 * s;
    float kr2 = k1 * s + k2 * c;
    bf162 kh = __floats2bfloat162_rn(kr1, kr2);
    bf162 kl = __floats2bfloat162_rn(kr1 - __bfloat162float(kh.x),
                                     kr2 - __bfloat162float(kh.y));
    *(bf162*)&g_K[base]      = kh;
    *(bf162*)&g_K[NX + base] = kl;
}

// ----------------------------------------------------------------------------
// Tensor-core GEMM (bf16 hi/lo): C = A * B^T, 3-term split.
// 128x128x32 tiles, 256 threads, 2-stage cp.async (.ca).
// Term order t2,t1,t3: Ah carried t2->t1, Bh carried t1->t3 (12 ldsm/ks).
// ----------------------------------------------------------------------------
#define BM 128
#define BN 128
#define BKT 32
#define SSTR 40
#define ARR_ELEMS (BM * SSTR)
#define STAGE_ELEMS (4 * ARR_ELEMS)
#define GEMM_SMEM_BYTES (2 * STAGE_ELEMS * 2)   // 81920

template<int SPLIT_OUT, int OFFA, int OFFB>
__device__ __forceinline__
void gemm3_body(const bf16* __restrict__ A, const bf16* __restrict__ B,
                float* __restrict__ C, bf16* __restrict__ Ch,
                int bx, int by)
{
    extern __shared__ bf16 smem[];
    const int tid  = threadIdx.x;
    const int lane = tid & 31;
    const int wid  = tid >> 5;
    const int wm   = (wid >> 2) * 64;
    const int wn   = (wid & 3) * 32;
    const int K = D_MODEL, N = D_MODEL;

    float acc[4][4][4];
#pragma unroll
    for (int mi = 0; mi < 4; mi++)
#pragma unroll
        for (int ni = 0; ni < 4; ni++)
#pragma unroll
            for (int e = 0; e < 4; e++) acc[mi][ni][e] = 0.0f;

    const int lrow = tid >> 1;
    const int lcol = (tid & 1) * 16;
    const bf16* gA = A + (size_t)(by * BM + lrow) * K + lcol;
    const bf16* gB = B + (size_t)(bx * BN + lrow) * K + lcol;

    uint32_t sbase = (uint32_t)__cvta_generic_to_shared(smem);
    uint32_t ldst  = (uint32_t)((lrow * SSTR + lcol) * 2);

    uint32_t aoff[4];
#pragma unroll
    for (int mi = 0; mi < 4; mi++)
        aoff[mi] = (uint32_t)(((wm + mi * 16 + (lane & 15)) * SSTR + (lane >> 4) * 8) * 2);
    uint32_t boff[2];
#pragma unroll
    for (int p = 0; p < 2; p++) {
        int g = lane >> 3;
        boff[p] = (uint32_t)(((wn + p * 16 + (g >> 1) * 8 + (lane & 7)) * SSTR + (g & 1) * 8) * 2);
    }

    const int NT = K / BKT;

    {
        uint32_t so = sbase;
        cp16a(so + ldst,                      gA);
        cp16a(so + ldst + 16,                 gA + 8);
        cp16a(so + ARR_ELEMS * 2 + ldst,      gA + OFFA);
        cp16a(so + ARR_ELEMS * 2 + ldst + 16, gA + OFFA + 8);
        cp16a(so + ARR_ELEMS * 4 + ldst,      gB);
        cp16a(so + ARR_ELEMS * 4 + ldst + 16, gB + 8);
        cp16a(so + ARR_ELEMS * 6 + ldst,      gB + OFFB);
        cp16a(so + ARR_ELEMS * 6 + ldst + 16, gB + OFFB + 8);
        cp_commit();
    }

    for (int kt = 0; kt < NT; kt++) {
        int cur = kt & 1;
        if (kt + 1 < NT) {
            uint32_t so = sbase + (uint32_t)(((kt + 1) & 1) * STAGE_ELEMS * 2);
            int kof = (kt + 1) * BKT;
            cp16a(so + ldst,                      gA + kof);
            cp16a(so + ldst + 16,                 gA + kof + 8);
            cp16a(so + ARR_ELEMS * 2 + ldst,      gA + OFFA + kof);
            cp16a(so + ARR_ELEMS * 2 + ldst + 16, gA + OFFA + kof + 8);
            cp16a(so + ARR_ELEMS * 4 + ldst,      gB + kof);
            cp16a(so + ARR_ELEMS * 4 + ldst + 16, gB + kof + 8);
            cp16a(so + ARR_ELEMS * 6 + ldst,      gB + OFFB + kof);
            cp16a(so + ARR_ELEMS * 6 + ldst + 16, gB + OFFB + kof + 8);
        }
        cp_commit();
        cp_wait1();
        __syncthreads();

        uint32_t sAh = sbase + (uint32_t)(cur * STAGE_ELEMS * 2);
        uint32_t sAl = sAh + ARR_ELEMS * 2;
        uint32_t sBh = sAh + ARR_ELEMS * 4;
        uint32_t sBl = sAh + ARR_ELEMS * 6;

#pragma unroll
        for (int ks = 0; ks < 2; ks++) {
            uint32_t kb = (uint32_t)(ks * 32);
            uint32_t ah[4][4], bb[2][4];

            // t2: Ah * Bl
#pragma unroll
            for (int mi = 0; mi < 4; mi++) ldsm_x4(ah[mi], sAh + aoff[mi] + kb);
#pragma unroll
            for (int p = 0; p < 2; p++)    ldsm_x4(bb[p], sBl + boff[p] + kb);
#pragma unroll
            for (int mi = 0; mi < 4; mi++)
#pragma unroll
                for (int ni = 0; ni < 4; ni++)
                    mma16816(acc[mi][ni], ah[mi], &bb[ni >> 1][(ni & 1) * 2]);

            // t1: Ah * Bh (reuse ah)
#pragma unroll
            for (int p = 0; p < 2; p++)    ldsm_x4(bb[p], sBh + boff[p] + kb);
#pragma unroll
            for (int mi = 0; mi < 4; mi++)
#pragma unroll
                for (int ni = 0; ni < 4; ni++)
                    mma16816(acc[mi][ni], ah[mi], &bb[ni >> 1][(ni & 1) * 2]);

            // t3: Al * Bh (reuse bb)
#pragma unroll
            for (int mi = 0; mi < 4; mi++) ldsm_x4(ah[mi], sAl + aoff[mi] + kb);
#pragma unroll
            for (int mi = 0; mi < 4; mi++)
#pragma unroll
                for (int ni = 0; ni < 4; ni++)
                    mma16816(acc[mi][ni], ah[mi], &bb[ni >> 1][(ni & 1) * 2]);
        }
        __syncthreads();
    }

#pragma unroll
    for (int mi = 0; mi < 4; mi++) {
        int r0 = by * BM + wm + mi * 16 + (lane >> 2);
#pragma unroll
        for (int ni = 0; ni < 4; ni++) {
            int cc = bx * BN + wn + ni * 8 + (lane & 3) * 2;
            if (SPLIT_OUT) {
                bf16* Cl = Ch + NX;
                float v0 = acc[mi][ni][0], v1 = acc[mi][ni][1];
                bf162 h0 = __floats2bfloat162_rn(v0, v1);
                bf162 l0 = __floats2bfloat162_rn(v0 - __bfloat162float(h0.x),
                                                 v1 - __bfloat162float(h0.y));
                *(bf162*)&Ch[(size_t)r0 * N + cc] = h0;
                *(bf162*)&Cl[(size_t)r0 * N + cc] = l0;
                float v2 = acc[mi][ni][2], v3 = acc[mi][ni][3];
                bf162 h1 = __floats2bfloat162_rn(v2, v3);
                bf162 l1 = __floats2bfloat162_rn(v2 - __bfloat162float(h1.x),
                                                 v3 - __bfloat162float(h1.y));
                *(bf162*)&Ch[(size_t)(r0 + 8) * N + cc] = h1;
                *(bf162*)&Cl[(size_t)(r0 + 8) * N + cc] = l1;
            } else {
                *(float2*)&C[(size_t)r0 * N + cc] =
                    make_float2(acc[mi][ni][0], acc[mi][ni][1]);
                *(float2*)&C[(size_t)(r0 + 8) * N + cc] =
                    make_float2(acc[mi][ni][2], acc[mi][ni][3]);
            }
        }
    }
}

__global__ __launch_bounds__(256, 2)
void qkv_tc()
{
    if (blockIdx.z == 0)
        gemm3_body<0, NX, NW>(g_x, g_Wq, g_Qf, nullptr, blockIdx.x, blockIdx.y);
    else if (blockIdx.z == 1)
        gemm3_body<0, NX, NW>(g_x, g_Wk, g_Kf, nullptr, blockIdx.x, blockIdx.y);
    else
        gemm3_body<1, NX, NW>(g_x, g_Wv, nullptr, g_V, blockIdx.x, blockIdx.y);
}

__global__ __launch_bounds__(256, 2)
void out_tc(float* __restrict__ out)
{
    gemm3_body<0, NX, NW>(g_ctx, g_Wo, out, nullptr, blockIdx.x, blockIdx.y);
}

// ----------------------------------------------------------------------------
// Tensor-core flash attention. Br=128, Bc=64, 256 threads, 2-stage cp.async
// (.ca — KV tiles are re-read by up to 16 CTAs of the same (b,h)) KV pipeline.
// Q fragments hoisted; QK term order t2,t1,t3.
// ----------------------------------------------------------------------------
#define ASTR 136
#define SQL_OFF (128 * ASTR)
#define SKV0 (2 * 128 * ASTR)
#define KV_STAGE (4 * 64 * ASTR)
#define ATTN_SMEM_BYTES ((SKV0 + 2 * KV_STAGE) * 2)

__global__ __launch_bounds__(256, 1)
void attn_tc()
{
    extern __shared__ bf16 sm[];
    const int tid  = threadIdx.x;
    const int lane = tid & 31;
    const int w    = tid >> 5;
    const int qt   = (int)gridDim.x - 1 - (int)blockIdx.x;
    const int bh   = blockIdx.y;
    const int b    = bh >> 4;
    const int h    = bh & 15;
    const int qrow0 = qt * 128;
    const int wrow  = w * 16;

    uint32_t sbase = (uint32_t)__cvta_generic_to_shared(sm);

    const int kvrow  = tid >> 2;
    const int kvcolb = (tid & 3) * 32;
    const size_t kvg = (size_t)(b * SEQ + kvrow) * D_MODEL + h * D_K + kvcolb;
    const uint32_t kvs = (uint32_t)((kvrow * ASTR + kvcolb) * 2);

    // ---- Q tile (hi/lo) -> smem ----
    {
        int row = tid >> 1, colb = (tid & 1) * 64;
        size_t gq = (size_t)(b * SEQ + qrow0 + row) * D_MODEL + h * D_K + colb;
        uint32_t sq = sbase + (uint32_t)((row * ASTR + colb) * 2);
#pragma unroll
        for (int cc = 0; cc < 8; cc++) {
            cp16a(sq + cc * 16,               g_Q + gq + cc * 8);
            cp16a(sq + SQL_OFF * 2 + cc * 16, g_Q + NX + gq + cc * 8);
        }
    }

    const int njt = 2 * qt + 2;

    // ---- KV tile 0 -> stage 0 ----
    {
        uint32_t sb = sbase + (uint32_t)(SKV0 * 2) + kvs;
#pragma unroll
        for (int cc = 0; cc < 4; cc++) {
            cp16a(sb + cc * 16,                     g_K + kvg + cc * 8);
            cp16a(sb + 64 * ASTR * 2 + cc * 16,     g_K + NX + kvg + cc * 8);
            cp16a(sb + 2 * 64 * ASTR * 2 + cc * 16, g_V + kvg + cc * 8);
            cp16a(sb + 3 * 64 * ASTR * 2 + cc * 16, g_V + NX + kvg + cc * 8);
        }
        cp_commit();
    }

    // ---- hoist Q fragments into registers (loop-invariant) ----
    uint32_t aoff = (uint32_t)(((wrow + (lane & 15)) * ASTR + (lane >> 4) * 8) * 2);
    cp_wait0();
    __syncthreads();
    uint32_t qh[8][4], ql[8][4];
#pragma unroll
    for (int ks = 0; ks < 8; ks++) {
        ldsm_x4(qh[ks], sbase + aoff + (uint32_t)(ks * 32));
        ldsm_x4(ql[ks], sbase + SQL_OFF * 2 + aoff + (uint32_t)(ks * 32));
    }

    float O[16][4];
#pragma unroll
    for (int nt = 0; nt < 16; nt++)
#pragma unroll
        for (int e = 0; e < 4; e++) O[nt][e] = 0.0f;
    float m_i[2] = {-1e30f, -1e30f};
    float l_i[2] = {0.0f, 0.0f};

    uint32_t boff[4];
#pragma unroll
    for (int p = 0; p < 4; p++) {
        int g = lane >> 3;
        boff[p] = (uint32_t)(((p * 16 + (g >> 1) * 8 + (lane & 7)) * ASTR + (g & 1) * 8) * 2);
    }
    int vrow = ((lane >> 3) & 1) * 8 + (lane & 7);
    int vcol = (lane >> 4) * 8;

    for (int j = 0; j < njt; j++) {
        int s = j & 1;
        if (j + 1 < njt) {
            uint32_t sb = sbase + (uint32_t)((SKV0 + (s ^ 1) * KV_STAGE) * 2) + kvs;
            size_t gb = kvg + (size_t)(j + 1) * 64 * D_MODEL;
#pragma unroll
            for (int cc = 0; cc < 4; cc++) {
                cp16a(sb + cc * 16,                     g_K + gb + cc * 8);
                cp16a(sb + 64 * ASTR * 2 + cc * 16,     g_K + NX + gb + cc * 8);
                cp16a(sb + 2 * 64 * ASTR * 2 + cc * 16, g_V + gb + cc * 8);
                cp16a(sb + 3 * 64 * ASTR * 2 + cc * 16, g_V + NX + gb + cc * 8);
            }
        }
        cp_commit();
        cp_wait1();
        __syncthreads();

        uint32_t skh = sbase + (uint32_t)((SKV0 + s * KV_STAGE) * 2);
        uint32_t skl = skh + 64 * ASTR * 2;
        uint32_t svh = skh + 2 * 64 * ASTR * 2;
        uint32_t svl = skh + 3 * 64 * ASTR * 2;

        bool active = (j * 64 <= qrow0 + wrow + 15);
        if (active) {
            // ---- S = Q K^T, terms t2(Qh·Kl), t1(Qh·Kh), t3(Ql·Kh) ----
            float S[8][4];
#pragma unroll
            for (int t = 0; t < 8; t++)
#pragma unroll
                for (int e = 0; e < 4; e++) S[t][e] = 0.0f;

#pragma unroll
            for (int ks = 0; ks < 8; ks++) {
                uint32_t kb = (uint32_t)(ks * 32);
                uint32_t bb[4][4];
#pragma unroll
                for (int p = 0; p < 4; p++) ldsm_x4(bb[p], skl + boff[p] + kb);
#pragma unroll
                for (int t = 0; t < 8; t++) mma16816(S[t], qh[ks], &bb[t >> 1][(t & 1) * 2]);
#pragma unroll
                for (int p = 0; p < 4; p++) ldsm_x4(bb[p], skh + boff[p] + kb);
#pragma unroll
                for (int t = 0; t < 8; t++) mma16816(S[t], qh[ks], &bb[t >> 1][(t & 1) * 2]);
#pragma unroll
                for (int t = 0; t < 8; t++) mma16816(S[t], ql[ks], &bb[t >> 1][(t & 1) * 2]);
            }

            // ---- causal mask ----
            int grow0 = qrow0 + wrow + (lane >> 2);
            int grow1 = grow0 + 8;
            if (j * 64 + 63 > qrow0 + wrow) {
#pragma unroll
                for (int t = 0; t < 8; t++) {
                    int c0 = j * 64 + t * 8 + 2 * (lane & 3);
                    if (c0     > grow0) S[t][0] = -1e30f;
                    if (c0 + 1 > grow0) S[t][1] = -1e30f;
                    if (c0     > grow1) S[t][2] = -1e30f;
                    if (c0 + 1 > grow1) S[t][3] = -1e30f;
                }
            }

            // ---- online softmax ----
            float mx0 = -1e30f, mx1 = -1e30f;
#pragma unroll
            for (int t = 0; t < 8; t++) {
                mx0 = fmaxf(mx0, fmaxf(S[t][0], S[t][1]));
                mx1 = fmaxf(mx1, fmaxf(S[t][2], S[t][3]));
            }
            mx0 = fmaxf(mx0, __shfl_xor_sync(0xffffffffu, mx0, 1));
            mx0 = fmaxf(mx0, __shfl_xor_sync(0xffffffffu, mx0, 2));
            mx1 = fmaxf(mx1, __shfl_xor_sync(0xffffffffu, mx1, 1));
            mx1 = fmaxf(mx1, __shfl_xor_sync(0xffffffffu, mx1, 2));

            float mn0 = fmaxf(m_i[0], mx0), mn1 = fmaxf(m_i[1], mx1);
            float al0 = __expf(m_i[0] - mn0), al1 = __expf(m_i[1] - mn1);
            m_i[0] = mn0; m_i[1] = mn1;

            float sum0 = 0.0f, sum1 = 0.0f;
#pragma unroll
            for (int t = 0; t < 8; t++) {
                S[t][0] = __expf(S[t][0] - mn0);
                S[t][1] = __expf(S[t][1] - mn0);
                S[t][2] = __expf(S[t][2] - mn1);
                S[t][3] = __expf(S[t][3] - mn1);
                sum0 += S[t][0] + S[t][1];
                sum1 += S[t][2] + S[t][3];
            }
            sum0 += __shfl_xor_sync(0xffffffffu, sum0, 1);
            sum0 += __shfl_xor_sync(0xffffffffu, sum0, 2);
            sum1 += __shfl_xor_sync(0xffffffffu, sum1, 1);
            sum1 += __shfl_xor_sync(0xffffffffu, sum1, 2);
            l_i[0] = l_i[0] * al0 + sum0;
            l_i[1] = l_i[1] * al1 + sum1;

#pragma unroll
            for (int nt = 0; nt < 16; nt++) {
                O[nt][0] *= al0; O[nt][1] *= al0;
                O[nt][2] *= al1; O[nt][3] *= al1;
            }

            // ---- O += P V (3-term; P hi/lo built per kb) ----
#pragma unroll
            for (int kb = 0; kb < 4; kb++) {
                uint32_t ph[4], pl[4];
#pragma unroll
                for (int u = 0; u < 2; u++) {
                    int t = 2 * kb + u;
                    bf162 h01 = __floats2bfloat162_rn(S[t][0], S[t][1]);
                    bf162 l01 = __floats2bfloat162_rn(S[t][0] - __bfloat162float(h01.x),
                                                      S[t][1] - __bfloat162float(h01.y));
                    bf162 h23 = __floats2bfloat162_rn(S[t][2], S[t][3]);
                    bf162 l23 = __floats2bfloat162_rn(S[t][2] - __bfloat162float(h23.x),
                                                      S[t][3] - __bfloat162float(h23.y));
                    ph[2 * u]     = *(uint32_t*)&h01;
                    pl[2 * u]     = *(uint32_t*)&l01;
                    ph[2 * u + 1] = *(uint32_t*)&h23;
                    pl[2 * u + 1] = *(uint32_t*)&l23;
                }
#pragma unroll
                for (int half = 0; half < 2; half++) {
                    uint32_t vb[4][4];
#pragma unroll
                    for (int i = 0; i < 4; i++)
                        ldsm_x4_t(vb[i], svh + (uint32_t)(((kb * 16 + vrow) * ASTR +
                                                (half * 4 + i) * 16 + vcol) * 2));
#pragma unroll
                    for (int nt = 0; nt < 8; nt++)
                        mma16816(O[half * 8 + nt], ph, &vb[nt >> 1][(nt & 1) * 2]);
#pragma unroll
                    for (int nt = 0; nt < 8; nt++)
                        mma16816(O[half * 8 + nt], pl, &vb[nt >> 1][(nt & 1) * 2]);
#pragma unroll
                    for (int i = 0; i < 4; i++)
                        ldsm_x4_t(vb[i], svl + (uint32_t)(((kb * 16 + vrow) * ASTR +
                                                (half * 4 + i) * 16 + vcol) * 2));
#pragma unroll
                    for (int nt = 0; nt < 8; nt++)
                        mma16816(O[half * 8 + nt], ph, &vb[nt >> 1][(nt & 1) * 2]);
                }
            }
        }
        __syncthreads();
    }

    float inv0 = 1.0f / l_i[0], inv1 = 1.0f / l_i[1];
    size_t gr0 = (size_t)(b * SEQ + qrow0 + wrow + (lane >> 2)) * D_MODEL + h * D_K;
    size_t gr1 = gr0 + (size_t)8 * D_MODEL;
#pragma unroll
    for (int nt = 0; nt < 16; nt++) {
        int d0 = nt * 8 + (lane & 3) * 2;
        float v0 = O[nt][0] * inv0, v1 = O[nt][1] * inv0;
        bf162 h0 = __floats2bfloat162_rn(v0, v1);
        bf162 l0 = __floats2bfloat162_rn(v0 - __bfloat162float(h0.x),
                                         v1 - __bfloat162float(h0.y));
        *(bf162*)&g_ctx[gr0 + d0]      = h0;
        *(bf162*)&g_ctx[NX + gr0 + d0] = l0;
        float v2 = O[nt][2] * inv1, v3 = O[nt][3] * inv1;
        bf162 h1 = __floats2bfloat162_rn(v2, v3);
        bf162 l1 = __floats2bfloat162_rn(v2 - __bfloat162float(h1.x),
                                         v3 - __bfloat162float(h1.y));
        *(bf162*)&g_ctx[gr1 + d0]      = h1;
        *(bf162*)&g_ctx[NX + gr1 + d0] = l1;
    }
}

// ----------------------------------------------------------------------------
// Launcher
// ----------------------------------------------------------------------------
extern "C" void kernel_launch(void* const* d_in, const int* in_sizes, int n_in,
                              void* d_out, int out_size)
{
    const float* x   = (const float*)d_in[0];
    const int*   pos = (const int*)d_in[1];
    const float* Wq  = (const float*)d_in[2];
    const float* Wk  = (const float*)d_in[3];
    const float* Wv  = (const float*)d_in[4];
    const float* Wo  = (const float*)d_in[5];
    float* out = (float*)d_out;

    {
        int nb = (NX / 4 + 255) / 256;
        split_all<<<dim3(nb, 5), 256>>>(x, Wq, Wk, Wv, Wo);
    }
    {
        int total = M_ROWS * HALF_DK;
        rope_table_kernel<<<(total + 255) / 256, 256>>>(pos);
    }

    cudaFuncSetAttribute(qkv_tc, cudaFuncAttributeMaxDynamicSharedMemorySize,
                         GEMM_SMEM_BYTES);
    cudaFuncSetAttribute(out_tc, cudaFuncAttributeMaxDynamicSharedMemorySize,
                         GEMM_SMEM_BYTES);
    cudaFuncSetAttribute(attn_tc, cudaFuncAttributeMaxDynamicSharedMemorySize,
                         ATTN_SMEM_BYTES);

    dim3 gthr(256);
    qkv_tc<<<dim3(D_MODEL / BN, M_ROWS / BM, 3), gthr, GEMM_SMEM_BYTES>>>();

    {
        int total = M_ROWS * NUM_HEADS * HALF_DK;
        rope_split_kernel<<<(total + 255) / 256, 256>>>();
    }

    attn_tc<<<dim3(SEQ / 128, BATCH * NUM_HEADS), gthr, ATTN_SMEM_BYTES>>>();

    out_tc<<<dim3(D_MODEL / BN, M_ROWS / BM), gthr, GEMM_SMEM_BYTES>>>(out);
}

// round 13
// speedup vs baseline: 1.0519x; 1.0519x over previous
#include <cuda_runtime.h>
#include <cuda_bf16.h>
#include <math.h>
#include <stdint.h>

// ----------------------------------------------------------------------------
// Problem constants
// ----------------------------------------------------------------------------
#define D_MODEL   2048
#define NUM_HEADS 16
#define D_K       128
#define HALF_DK   64
#define BATCH     2
#define SEQ       2048
#define M_ROWS    (BATCH * SEQ)
#define NX (M_ROWS * D_MODEL)
#define NW (D_MODEL * D_MODEL)

typedef __nv_bfloat16  bf16;
typedef __nv_bfloat162 bf162;

// ----------------------------------------------------------------------------
// Scratch (device globals; hi at [0,N), lo at [N,2N)). Device-code refs only.
// ----------------------------------------------------------------------------
__device__ float g_Qf[NX];
__device__ float g_Kf[NX];

__device__ bf16 g_x [2 * NX];
__device__ bf16 g_Wq[2 * NW], g_Wk[2 * NW], g_Wv[2 * NW], g_Wo[2 * NW];
__device__ bf16 g_Q [2 * NX], g_K [2 * NX], g_V [2 * NX], g_ctx[2 * NX];
__device__ float2 g_rope[M_ROWS * HALF_DK];   // (cos, sin) per (row, pair)

// ----------------------------------------------------------------------------
// PTX helpers
// ----------------------------------------------------------------------------
__device__ __forceinline__ void ldsm_x4(uint32_t* r, uint32_t addr) {
    asm volatile("ldmatrix.sync.aligned.m8n8.x4.shared.b16 {%0,%1,%2,%3}, [%4];"
                 : "=r"(r[0]), "=r"(r[1]), "=r"(r[2]), "=r"(r[3]) : "r"(addr));
}
__device__ __forceinline__ void ldsm_x4_t(uint32_t* r, uint32_t addr) {
    asm volatile("ldmatrix.sync.aligned.m8n8.x4.trans.shared.b16 {%0,%1,%2,%3}, [%4];"
                 : "=r"(r[0]), "=r"(r[1]), "=r"(r[2]), "=r"(r[3]) : "r"(addr));
}
__device__ __forceinline__ void mma16816(float* c, const uint32_t* a, const uint32_t* b) {
    asm volatile("mma.sync.aligned.m16n8k16.row.col.f32.bf16.bf16.f32 "
                 "{%0,%1,%2,%3},{%4,%5,%6,%7},{%8,%9},{%0,%1,%2,%3};"
                 : "+f"(c[0]), "+f"(c[1]), "+f"(c[2]), "+f"(c[3])
                 : "r"(a[0]), "r"(a[1]), "r"(a[2]), "r"(a[3]), "r"(b[0]), "r"(b[1]));
}
// .ca for GEMM tiles (R7-measured best), .cg for attention KV (R8/R11-measured best)
__device__ __forceinline__ void cp16a(uint32_t dst, const void* src) {
    asm volatile("cp.async.ca.shared.global [%0], [%1], 16;" :: "r"(dst), "l"(src));
}
__device__ __forceinline__ void cp16g(uint32_t dst, const void* src) {
    asm volatile("cp.async.cg.shared.global [%0], [%1], 16;" :: "r"(dst), "l"(src));
}
__device__ __forceinline__ void cp_commit() { asm volatile("cp.async.commit_group;"); }
__device__ __forceinline__ void cp_wait1()  { asm volatile("cp.async.wait_group 1;"); }
__device__ __forceinline__ void cp_wait0()  { asm volatile("cp.async.wait_group 0;"); }

// ----------------------------------------------------------------------------
// Split all 5 inputs fp32 -> (hi, lo) bf16. Dest selected in device code.
// ----------------------------------------------------------------------------
__global__ void split_all(const float* __restrict__ x,
                          const float* __restrict__ Wq,
                          const float* __restrict__ Wk,
                          const float* __restrict__ Wv,
                          const float* __restrict__ Wo)
{
    const float* src;
    bf16 *h, *l;
    int n4;
    switch (blockIdx.y) {
        case 0:  src = x;  h = g_x;  l = g_x  + NX; n4 = NX / 4; break;
        case 1:  src = Wq; h = g_Wq; l = g_Wq + NW; n4 = NW / 4; break;
        case 2:  src = Wk; h = g_Wk; l = g_Wk + NW; n4 = NW / 4; break;
        case 3:  src = Wv; h = g_Wv; l = g_Wv + NW; n4 = NW / 4; break;
        default: src = Wo; h = g_Wo; l = g_Wo + NW; n4 = NW / 4; break;
    }
    int i = blockIdx.x * blockDim.x + threadIdx.x;
    if (i >= n4) return;
    float4 v = ((const float4*)src)[i];
    float vv[4] = {v.x, v.y, v.z, v.w};
    bf16 hh[4], ll[4];
#pragma unroll
    for (int e = 0; e < 4; e++) {
        hh[e] = __float2bfloat16(vv[e]);
        ll[e] = __float2bfloat16(vv[e] - __bfloat162float(hh[e]));
    }
    ((bf162*)h)[i * 2]     = bf162(hh[0], hh[1]);
    ((bf162*)h)[i * 2 + 1] = bf162(hh[2], hh[3]);
    ((bf162*)l)[i * 2]     = bf162(ll[0], ll[1]);
    ((bf162*)l)[i * 2 + 1] = bf162(ll[2], ll[3]);
}

// ----------------------------------------------------------------------------
// RoPE phase 1: cos/sin table, fp64 angles, one entry per (row, pair).
// ----------------------------------------------------------------------------
__global__ void rope_table_kernel(const int* __restrict__ pos)
{
    int idx = blockIdx.x * blockDim.x + threadIdx.x;
    if (idx >= M_ROWS * HALF_DK) return;
    int i = idx % HALF_DK;
    int m = idx / HALF_DK;
    double ang = (double)pos[m] * pow(10000.0, -(double)i / 64.0);
    g_rope[idx] = make_float2((float)cos(ang), (float)sin(ang));
}

// ----------------------------------------------------------------------------
// RoPE phase 2: apply rotation (fp32) + hi/lo split; Q pre-scaled by 1/sqrt(dk).
// ----------------------------------------------------------------------------
__global__ void rope_split_kernel()
{
    int idx = blockIdx.x * blockDim.x + threadIdx.x;
    const int total = M_ROWS * NUM_HEADS * HALF_DK;
    if (idx >= total) return;

    int i = idx % HALF_DK;
    int h = (idx / HALF_DK) % NUM_HEADS;
    int m = idx / (HALF_DK * NUM_HEADS);

    float2 cs = g_rope[m * HALF_DK + i];
    float c = cs.x, s = cs.y;
    const float qscale = 0.08838834764831845f;

    size_t base = (size_t)m * D_MODEL + h * D_K + 2 * i;

    float q1 = g_Qf[base], q2 = g_Qf[base + 1];
    float qr1 = (q1 * c - q2 * s) * qscale;
    float qr2 = (q1 * s + q2 * c) * qscale;
    bf162 qh = __floats2bfloat162_rn(qr1, qr2);
    bf162 ql = __floats2bfloat162_rn(qr1 - __bfloat162float(qh.x),
                                     qr2 - __bfloat162float(qh.y));
    *(bf162*)&g_Q[base]      = qh;
    *(bf162*)&g_Q[NX + base] = ql;

    float k1 = g_Kf[base], k2 = g_Kf[base + 1];
    float kr1 = k1 * c - k2 * s;
    float kr2 = k1 * s + k2 * c;
    bf162 kh = __floats2bfloat162_rn(kr1, kr2);
    bf162 kl = __floats2bfloat162_rn(kr1 - __bfloat162float(kh.x),
                                     kr2 - __bfloat162float(kh.y));
    *(bf162*)&g_K[base]      = kh;
    *(bf162*)&g_K[NX + base] = kl;
}

// ----------------------------------------------------------------------------
// Tensor-core GEMM (bf16 hi/lo): C = A * B^T, 3-term split.
// 128x128x32 tiles, 256 threads, 2-stage cp.async (.ca).
// Term order t2,t1,t3: Ah carried t2->t1, Bh carried t1->t3 (12 ldsm/ks).
// ----------------------------------------------------------------------------
#define BM 128
#define BN 128
#define BKT 32
#define SSTR 40
#define ARR_ELEMS (BM * SSTR)
#define STAGE_ELEMS (4 * ARR_ELEMS)
#define GEMM_SMEM_BYTES (2 * STAGE_ELEMS * 2)   // 81920

template<int SPLIT_OUT, int OFFA, int OFFB>
__device__ __forceinline__
void gemm3_body(const bf16* __restrict__ A, const bf16* __restrict__ B,
                float* __restrict__ C, bf16* __restrict__ Ch,
                int bx, int by)
{
    extern __shared__ bf16 smem[];
    const int tid  = threadIdx.x;
    const int lane = tid & 31;
    const int wid  = tid >> 5;
    const int wm   = (wid >> 2) * 64;
    const int wn   = (wid & 3) * 32;
    const int K = D_MODEL, N = D_MODEL;

    float acc[4][4][4];
#pragma unroll
    for (int mi = 0; mi < 4; mi++)
#pragma unroll
        for (int ni = 0; ni < 4; ni++)
#pragma unroll
            for (int e = 0; e < 4; e++) acc[mi][ni][e] = 0.0f;

    const int lrow = tid >> 1;
    const int lcol = (tid & 1) * 16;
    const bf16* gA = A + (size_t)(by * BM + lrow) * K + lcol;
    const bf16* gB = B + (size_t)(bx * BN + lrow) * K + lcol;

    uint32_t sbase = (uint32_t)__cvta_generic_to_shared(smem);
    uint32_t ldst  = (uint32_t)((lrow * SSTR + lcol) * 2);

    uint32_t aoff[4];
#pragma unroll
    for (int mi = 0; mi < 4; mi++)
        aoff[mi] = (uint32_t)(((wm + mi * 16 + (lane & 15)) * SSTR + (lane >> 4) * 8) * 2);
    uint32_t boff[2];
#pragma unroll
    for (int p = 0; p < 2; p++) {
        int g = lane >> 3;
        boff[p] = (uint32_t)(((wn + p * 16 + (g >> 1) * 8 + (lane & 7)) * SSTR + (g & 1) * 8) * 2);
    }

    const int NT = K / BKT;

    {
        uint32_t so = sbase;
        cp16a(so + ldst,                      gA);
        cp16a(so + ldst + 16,                 gA + 8);
        cp16a(so + ARR_ELEMS * 2 + ldst,      gA + OFFA);
        cp16a(so + ARR_ELEMS * 2 + ldst + 16, gA + OFFA + 8);
        cp16a(so + ARR_ELEMS * 4 + ldst,      gB);
        cp16a(so + ARR_ELEMS * 4 + ldst + 16, gB + 8);
        cp16a(so + ARR_ELEMS * 6 + ldst,      gB + OFFB);
        cp16a(so + ARR_ELEMS * 6 + ldst + 16, gB + OFFB + 8);
        cp_commit();
    }

    for (int kt = 0; kt < NT; kt++) {
        int cur = kt & 1;
        if (kt + 1 < NT) {
            uint32_t so = sbase + (uint32_t)(((kt + 1) & 1) * STAGE_ELEMS * 2);
            int kof = (kt + 1) * BKT;
            cp16a(so + ldst,                      gA + kof);
            cp16a(so + ldst + 16,                 gA + kof + 8);
            cp16a(so + ARR_ELEMS * 2 + ldst,      gA + OFFA + kof);
            cp16a(so + ARR_ELEMS * 2 + ldst + 16, gA + OFFA + kof + 8);
            cp16a(so + ARR_ELEMS * 4 + ldst,      gB + kof);
            cp16a(so + ARR_ELEMS * 4 + ldst + 16, gB + kof + 8);
            cp16a(so + ARR_ELEMS * 6 + ldst,      gB + OFFB + kof);
            cp16a(so + ARR_ELEMS * 6 + ldst + 16, gB + OFFB + kof + 8);
        }
        cp_commit();
        cp_wait1();
        __syncthreads();

        uint32_t sAh = sbase + (uint32_t)(cur * STAGE_ELEMS * 2);
        uint32_t sAl = sAh + ARR_ELEMS * 2;
        uint32_t sBh = sAh + ARR_ELEMS * 4;
        uint32_t sBl = sAh + ARR_ELEMS * 6;

#pragma unroll
        for (int ks = 0; ks < 2; ks++) {
            uint32_t kb = (uint32_t)(ks * 32);
            uint32_t ah[4][4], bb[2][4];

            // t2: Ah * Bl
#pragma unroll
            for (int mi = 0; mi < 4; mi++) ldsm_x4(ah[mi], sAh + aoff[mi] + kb);
#pragma unroll
            for (int p = 0; p < 2; p++)    ldsm_x4(bb[p], sBl + boff[p] + kb);
#pragma unroll
            for (int mi = 0; mi < 4; mi++)
#pragma unroll
                for (int ni = 0; ni < 4; ni++)
                    mma16816(acc[mi][ni], ah[mi], &bb[ni >> 1][(ni & 1) * 2]);

            // t1: Ah * Bh (reuse ah)
#pragma unroll
            for (int p = 0; p < 2; p++)    ldsm_x4(bb[p], sBh + boff[p] + kb);
#pragma unroll
            for (int mi = 0; mi < 4; mi++)
#pragma unroll
                for (int ni = 0; ni < 4; ni++)
                    mma16816(acc[mi][ni], ah[mi], &bb[ni >> 1][(ni & 1) * 2]);

            // t3: Al * Bh (reuse bb)
#pragma unroll
            for (int mi = 0; mi < 4; mi++) ldsm_x4(ah[mi], sAl + aoff[mi] + kb);
#pragma unroll
            for (int mi = 0; mi < 4; mi++)
#pragma unroll
                for (int ni = 0; ni < 4; ni++)
                    mma16816(acc[mi][ni], ah[mi], &bb[ni >> 1][(ni & 1) * 2]);
        }
        __syncthreads();
    }

#pragma unroll
    for (int mi = 0; mi < 4; mi++) {
        int r0 = by * BM + wm + mi * 16 + (lane >> 2);
#pragma unroll
        for (int ni = 0; ni < 4; ni++) {
            int cc = bx * BN + wn + ni * 8 + (lane & 3) * 2;
            if (SPLIT_OUT) {
                bf16* Cl = Ch + NX;
                float v0 = acc[mi][ni][0], v1 = acc[mi][ni][1];
                bf162 h0 = __floats2bfloat162_rn(v0, v1);
                bf162 l0 = __floats2bfloat162_rn(v0 - __bfloat162float(h0.x),
                                                 v1 - __bfloat162float(h0.y));
                *(bf162*)&Ch[(size_t)r0 * N + cc] = h0;
                *(bf162*)&Cl[(size_t)r0 * N + cc] = l0;
                float v2 = acc[mi][ni][2], v3 = acc[mi][ni][3];
                bf162 h1 = __floats2bfloat162_rn(v2, v3);
                bf162 l1 = __floats2bfloat162_rn(v2 - __bfloat162float(h1.x),
                                                 v3 - __bfloat162float(h1.y));
                *(bf162*)&Ch[(size_t)(r0 + 8) * N + cc] = h1;
                *(bf162*)&Cl[(size_t)(r0 + 8) * N + cc] = l1;
            } else {
                *(float2*)&C[(size_t)r0 * N + cc] =
                    make_float2(acc[mi][ni][0], acc[mi][ni][1]);
                *(float2*)&C[(size_t)(r0 + 8) * N + cc] =
                    make_float2(acc[mi][ni][2], acc[mi][ni][3]);
            }
        }
    }
}

__global__ __launch_bounds__(256, 2)
void qkv_tc()
{
    if (blockIdx.z == 0)
        gemm3_body<0, NX, NW>(g_x, g_Wq, g_Qf, nullptr, blockIdx.x, blockIdx.y);
    else if (blockIdx.z == 1)
        gemm3_body<0, NX, NW>(g_x, g_Wk, g_Kf, nullptr, blockIdx.x, blockIdx.y);
    else
        gemm3_body<1, NX, NW>(g_x, g_Wv, nullptr, g_V, blockIdx.x, blockIdx.y);
}

__global__ __launch_bounds__(256, 2)
void out_tc(float* __restrict__ out)
{
    gemm3_body<0, NX, NW>(g_ctx, g_Wo, out, nullptr, blockIdx.x, blockIdx.y);
}

// ----------------------------------------------------------------------------
// Tensor-core flash attention. Br=128, Bc=64, 256 threads, 2-stage cp.async
// (.cg) KV pipeline. Q fragments hoisted; QK term order t2,t1,t3.
// ----------------------------------------------------------------------------
#define ASTR 136
#define SQL_OFF (128 * ASTR)
#define SKV0 (2 * 128 * ASTR)
#define KV_STAGE (4 * 64 * ASTR)
#define ATTN_SMEM_BYTES ((SKV0 + 2 * KV_STAGE) * 2)

__global__ __launch_bounds__(256, 1)
void attn_tc()
{
    extern __shared__ bf16 sm[];
    const int tid  = threadIdx.x;
    const int lane = tid & 31;
    const int w    = tid >> 5;
    const int qt   = (int)gridDim.x - 1 - (int)blockIdx.x;
    const int bh   = blockIdx.y;
    const int b    = bh >> 4;
    const int h    = bh & 15;
    const int qrow0 = qt * 128;
    const int wrow  = w * 16;

    uint32_t sbase = (uint32_t)__cvta_generic_to_shared(sm);

    const int kvrow  = tid >> 2;
    const int kvcolb = (tid & 3) * 32;
    const size_t kvg = (size_t)(b * SEQ + kvrow) * D_MODEL + h * D_K + kvcolb;
    const uint32_t kvs = (uint32_t)((kvrow * ASTR + kvcolb) * 2);

    // ---- Q tile (hi/lo) -> smem ----
    {
        int row = tid >> 1, colb = (tid & 1) * 64;
        size_t gq = (size_t)(b * SEQ + qrow0 + row) * D_MODEL + h * D_K + colb;
        uint32_t sq = sbase + (uint32_t)((row * ASTR + colb) * 2);
#pragma unroll
        for (int cc = 0; cc < 8; cc++) {
            cp16g(sq + cc * 16,               g_Q + gq + cc * 8);
            cp16g(sq + SQL_OFF * 2 + cc * 16, g_Q + NX + gq + cc * 8);
        }
    }

    const int njt = 2 * qt + 2;

    // ---- KV tile 0 -> stage 0 ----
    {
        uint32_t sb = sbase + (uint32_t)(SKV0 * 2) + kvs;
#pragma unroll
        for (int cc = 0; cc < 4; cc++) {
            cp16g(sb + cc * 16,                     g_K + kvg + cc * 8);
            cp16g(sb + 64 * ASTR * 2 + cc * 16,     g_K + NX + kvg + cc * 8);
            cp16g(sb + 2 * 64 * ASTR * 2 + cc * 16, g_V + kvg + cc * 8);
            cp16g(sb + 3 * 64 * ASTR * 2 + cc * 16, g_V + NX + kvg + cc * 8);
        }
        cp_commit();
    }

    // ---- hoist Q fragments into registers (loop-invariant) ----
    uint32_t aoff = (uint32_t)(((wrow + (lane & 15)) * ASTR + (lane >> 4) * 8) * 2);
    cp_wait0();
    __syncthreads();
    uint32_t qh[8][4], ql[8][4];
#pragma unroll
    for (int ks = 0; ks < 8; ks++) {
        ldsm_x4(qh[ks], sbase + aoff + (uint32_t)(ks * 32));
        ldsm_x4(ql[ks], sbase + SQL_OFF * 2 + aoff + (uint32_t)(ks * 32));
    }

    float O[16][4];
#pragma unroll
    for (int nt = 0; nt < 16; nt++)
#pragma unroll
        for (int e = 0; e < 4; e++) O[nt][e] = 0.0f;
    float m_i[2] = {-1e30f, -1e30f};
    float l_i[2] = {0.0f, 0.0f};

    uint32_t boff[4];
#pragma unroll
    for (int p = 0; p < 4; p++) {
        int g = lane >> 3;
        boff[p] = (uint32_t)(((p * 16 + (g >> 1) * 8 + (lane & 7)) * ASTR + (g & 1) * 8) * 2);
    }
    int vrow = ((lane >> 3) & 1) * 8 + (lane & 7);
    int vcol = (lane >> 4) * 8;

    for (int j = 0; j < njt; j++) {
        int s = j & 1;
        if (j + 1 < njt) {
            uint32_t sb = sbase + (uint32_t)((SKV0 + (s ^ 1) * KV_STAGE) * 2) + kvs;
            size_t gb = kvg + (size_t)(j + 1) * 64 * D_MODEL;
#pragma unroll
            for (int cc = 0; cc < 4; cc++) {
                cp16g(sb + cc * 16,                     g_K + gb + cc * 8);
                cp16g(sb + 64 * ASTR * 2 + cc * 16,     g_K + NX + gb + cc * 8);
                cp16g(sb + 2 * 64 * ASTR * 2 + cc * 16, g_V + gb + cc * 8);
                cp16g(sb + 3 * 64 * ASTR * 2 + cc * 16, g_V + NX + gb + cc * 8);
            }
        }
        cp_commit();
        cp_wait1();
        __syncthreads();

        uint32_t skh = sbase + (uint32_t)((SKV0 + s * KV_STAGE) * 2);
        uint32_t skl = skh + 64 * ASTR * 2;
        uint32_t svh = skh + 2 * 64 * ASTR * 2;
        uint32_t svl = skh + 3 * 64 * ASTR * 2;

        bool active = (j * 64 <= qrow0 + wrow + 15);
        if (active) {
            // ---- S = Q K^T, terms t2(Qh·Kl), t1(Qh·Kh), t3(Ql·Kh) ----
            float S[8][4];
#pragma unroll
            for (int t = 0; t < 8; t++)
#pragma unroll
                for (int e = 0; e < 4; e++) S[t][e] = 0.0f;

#pragma unroll
            for (int ks = 0; ks < 8; ks++) {
                uint32_t kb = (uint32_t)(ks * 32);
                uint32_t bb[4][4];
#pragma unroll
                for (int p = 0; p < 4; p++) ldsm_x4(bb[p], skl + boff[p] + kb);
#pragma unroll
                for (int t = 0; t < 8; t++) mma16816(S[t], qh[ks], &bb[t >> 1][(t & 1) * 2]);
#pragma unroll
                for (int p = 0; p < 4; p++) ldsm_x4(bb[p], skh + boff[p] + kb);
#pragma unroll
                for (int t = 0; t < 8; t++) mma16816(S[t], qh[ks], &bb[t >> 1][(t & 1) * 2]);
#pragma unroll
                for (int t = 0; t < 8; t++) mma16816(S[t], ql[ks], &bb[t >> 1][(t & 1) * 2]);
            }

            // ---- causal mask ----
            int grow0 = qrow0 + wrow + (lane >> 2);
            int grow1 = grow0 + 8;
            if (j * 64 + 63 > qrow0 + wrow) {
#pragma unroll
                for (int t = 0; t < 8; t++) {
                    int c0 = j * 64 + t * 8 + 2 * (lane & 3);
                    if (c0     > grow0) S[t][0] = -1e30f;
                    if (c0 + 1 > grow0) S[t][1] = -1e30f;
                    if (c0     > grow1) S[t][2] = -1e30f;
                    if (c0 + 1 > grow1) S[t][3] = -1e30f;
                }
            }

            // ---- online softmax ----
            float mx0 = -1e30f, mx1 = -1e30f;
#pragma unroll
            for (int t = 0; t < 8; t++) {
                mx0 = fmaxf(mx0, fmaxf(S[t][0], S[t][1]));
                mx1 = fmaxf(mx1, fmaxf(S[t][2], S[t][3]));
            }
            mx0 = fmaxf(mx0, __shfl_xor_sync(0xffffffffu, mx0, 1));
            mx0 = fmaxf(mx0, __shfl_xor_sync(0xffffffffu, mx0, 2));
            mx1 = fmaxf(mx1, __shfl_xor_sync(0xffffffffu, mx1, 1));
            mx1 = fmaxf(mx1, __shfl_xor_sync(0xffffffffu, mx1, 2));

            float mn0 = fmaxf(m_i[0], mx0), mn1 = fmaxf(m_i[1], mx1);
            float al0 = __expf(m_i[0] - mn0), al1 = __expf(m_i[1] - mn1);
            m_i[0] = mn0; m_i[1] = mn1;

            float sum0 = 0.0f, sum1 = 0.0f;
#pragma unroll
            for (int t = 0; t < 8; t++) {
                S[t][0] = __expf(S[t][0] - mn0);
                S[t][1] = __expf(S[t][1] - mn0);
                S[t][2] = __expf(S[t][2] - mn1);
                S[t][3] = __expf(S[t][3] - mn1);
                sum0 += S[t][0] + S[t][1];
                sum1 += S[t][2] + S[t][3];
            }
            sum0 += __shfl_xor_sync(0xffffffffu, sum0, 1);
            sum0 += __shfl_xor_sync(0xffffffffu, sum0, 2);
            sum1 += __shfl_xor_sync(0xffffffffu, sum1, 1);
            sum1 += __shfl_xor_sync(0xffffffffu, sum1, 2);
            l_i[0] = l_i[0] * al0 + sum0;
            l_i[1] = l_i[1] * al1 + sum1;

#pragma unroll
            for (int nt = 0; nt < 16; nt++) {
                O[nt][0] *= al0; O[nt][1] *= al0;
                O[nt][2] *= al1; O[nt][3] *= al1;
            }

            // ---- O += P V (3-term; P hi/lo built per kb) ----
#pragma unroll
            for (int kb = 0; kb < 4; kb++) {
                uint32_t ph[4], pl[4];
#pragma unroll
                for (int u = 0; u < 2; u++) {
                    int t = 2 * kb + u;
                    bf162 h01 = __floats2bfloat162_rn(S[t][0], S[t][1]);
                    bf162 l01 = __floats2bfloat162_rn(S[t][0] - __bfloat162float(h01.x),
                                                      S[t][1] - __bfloat162float(h01.y));
                    bf162 h23 = __floats2bfloat162_rn(S[t][2], S[t][3]);
                    bf162 l23 = __floats2bfloat162_rn(S[t][2] - __bfloat162float(h23.x),
                                                      S[t][3] - __bfloat162float(h23.y));
                    ph[2 * u]     = *(uint32_t*)&h01;
                    pl[2 * u]     = *(uint32_t*)&l01;
                    ph[2 * u + 1] = *(uint32_t*)&h23;
                    pl[2 * u + 1] = *(uint32_t*)&l23;
                }
#pragma unroll
                for (int half = 0; half < 2; half++) {
                    uint32_t vb[4][4];
#pragma unroll
                    for (int i = 0; i < 4; i++)
                        ldsm_x4_t(vb[i], svh + (uint32_t)(((kb * 16 + vrow) * ASTR +
                                                (half * 4 + i) * 16 + vcol) * 2));
#pragma unroll
                    for (int nt = 0; nt < 8; nt++)
                        mma16816(O[half * 8 + nt], ph, &vb[nt >> 1][(nt & 1) * 2]);
#pragma unroll
                    for (int nt = 0; nt < 8; nt++)
                        mma16816(O[half * 8 + nt], pl, &vb[nt >> 1][(nt & 1) * 2]);
#pragma unroll
                    for (int i = 0; i < 4; i++)
                        ldsm_x4_t(vb[i], svl + (uint32_t)(((kb * 16 + vrow) * ASTR +
                                                (half * 4 + i) * 16 + vcol) * 2));
#pragma unroll
                    for (int nt = 0; nt < 8; nt++)
                        mma16816(O[half * 8 + nt], ph, &vb[nt >> 1][(nt & 1) * 2]);
                }
            }
        }
        __syncthreads();
    }

    float inv0 = 1.0f / l_i[0], inv1 = 1.0f / l_i[1];
    size_t gr0 = (size_t)(b * SEQ + qrow0 + wrow + (lane >> 2)) * D_MODEL + h * D_K;
    size_t gr1 = gr0 + (size_t)8 * D_MODEL;
#pragma unroll
    for (int nt = 0; nt < 16; nt++) {
        int d0 = nt * 8 + (lane & 3) * 2;
        float v0 = O[nt][0] * inv0, v1 = O[nt][1] * inv0;
        bf162 h0 = __floats2bfloat162_rn(v0, v1);
        bf162 l0 = __floats2bfloat162_rn(v0 - __bfloat162float(h0.x),
                                         v1 - __bfloat162float(h0.y));
        *(bf162*)&g_ctx[gr0 + d0]      = h0;
        *(bf162*)&g_ctx[NX + gr0 + d0] = l0;
        float v2 = O[nt][2] * inv1, v3 = O[nt][3] * inv1;
        bf162 h1 = __floats2bfloat162_rn(v2, v3);
        bf162 l1 = __floats2bfloat162_rn(v2 - __bfloat162float(h1.x),
                                         v3 - __bfloat162float(h1.y));
        *(bf162*)&g_ctx[gr1 + d0]      = h1;
        *(bf162*)&g_ctx[NX + gr1 + d0] = l1;
    }
}

// ----------------------------------------------------------------------------
// Launcher
// ----------------------------------------------------------------------------
extern "C" void kernel_launch(void* const* d_in, const int* in_sizes, int n_in,
                              void* d_out, int out_size)
{
    const float* x   = (const float*)d_in[0];
    const int*   pos = (const int*)d_in[1];
    const float* Wq  = (const float*)d_in[2];
    const float* Wk  = (const float*)d_in[3];
    const float* Wv  = (const float*)d_in[4];
    const float* Wo  = (const float*)d_in[5];
    float* out = (float*)d_out;

    {
        int nb = (NX / 4 + 255) / 256;
        split_all<<<dim3(nb, 5), 256>>>(x, Wq, Wk, Wv, Wo);
    }
    {
        int total = M_ROWS * HALF_DK;
        rope_table_kernel<<<(total + 255) / 256, 256>>>(pos);
    }

    cudaFuncSetAttribute(qkv_tc, cudaFuncAttributeMaxDynamicSharedMemorySize,
                         GEMM_SMEM_BYTES);
    cudaFuncSetAttribute(out_tc, cudaFuncAttributeMaxDynamicSharedMemorySize,
                         GEMM_SMEM_BYTES);
    cudaFuncSetAttribute(attn_tc, cudaFuncAttributeMaxDynamicSharedMemorySize,
                         ATTN_SMEM_BYTES);

    dim3 gthr(256);
    qkv_tc<<<dim3(D_MODEL / BN, M_ROWS / BM, 3), gthr, GEMM_SMEM_BYTES>>>();

    {
        int total = M_ROWS * NUM_HEADS * HALF_DK;
        rope_split_kernel<<<(total + 255) / 256, 256>>>();
    }

    attn_tc<<<dim3(SEQ / 128, BATCH * NUM_HEADS), gthr, ATTN_SMEM_BYTES>>>();

    out_tc<<<dim3(D_MODEL / BN, M_ROWS / BM), gthr, GEMM_SMEM_BYTES>>>(out);
}

// round 14
// speedup vs baseline: 1.0556x; 1.0036x over previous
#include <cuda_runtime.h>
#include <cuda_bf16.h>
#include <math.h>
#include <stdint.h>

// ----------------------------------------------------------------------------
// Problem constants
// ----------------------------------------------------------------------------
#define D_MODEL   2048
#define NUM_HEADS 16
#define D_K       128
#define HALF_DK   64
#define BATCH     2
#define SEQ       2048
#define M_ROWS    (BATCH * SEQ)
#define NX (M_ROWS * D_MODEL)
#define NW (D_MODEL * D_MODEL)

typedef __nv_bfloat16  bf16;
typedef __nv_bfloat162 bf162;

// ----------------------------------------------------------------------------
// Scratch (device globals; hi at [0,N), lo at [N,2N)). Device-code refs only.
// ----------------------------------------------------------------------------
__device__ bf16 g_x [2 * NX];
__device__ bf16 g_Wq[2 * NW], g_Wk[2 * NW], g_Wv[2 * NW], g_Wo[2 * NW];
__device__ bf16 g_Q [2 * NX], g_K [2 * NX], g_V [2 * NX], g_ctx[2 * NX];
__device__ float2 g_rope[M_ROWS * HALF_DK];   // (cos, sin) per (row, pair)

// ----------------------------------------------------------------------------
// PTX helpers
// ----------------------------------------------------------------------------
__device__ __forceinline__ void ldsm_x4(uint32_t* r, uint32_t addr) {
    asm volatile("ldmatrix.sync.aligned.m8n8.x4.shared.b16 {%0,%1,%2,%3}, [%4];"
                 : "=r"(r[0]), "=r"(r[1]), "=r"(r[2]), "=r"(r[3]) : "r"(addr));
}
__device__ __forceinline__ void ldsm_x4_t(uint32_t* r, uint32_t addr) {
    asm volatile("ldmatrix.sync.aligned.m8n8.x4.trans.shared.b16 {%0,%1,%2,%3}, [%4];"
                 : "=r"(r[0]), "=r"(r[1]), "=r"(r[2]), "=r"(r[3]) : "r"(addr));
}
__device__ __forceinline__ void mma16816(float* c, const uint32_t* a, const uint32_t* b) {
    asm volatile("mma.sync.aligned.m16n8k16.row.col.f32.bf16.bf16.f32 "
                 "{%0,%1,%2,%3},{%4,%5,%6,%7},{%8,%9},{%0,%1,%2,%3};"
                 : "+f"(c[0]), "+f"(c[1]), "+f"(c[2]), "+f"(c[3])
                 : "r"(a[0]), "r"(a[1]), "r"(a[2]), "r"(a[3]), "r"(b[0]), "r"(b[1]));
}
// .ca for GEMM tiles (R7/R13-measured), .cg for attention KV (R8/R13-measured)
__device__ __forceinline__ void cp16a(uint32_t dst, const void* src) {
    asm volatile("cp.async.ca.shared.global [%0], [%1], 16;" :: "r"(dst), "l"(src));
}
__device__ __forceinline__ void cp16g(uint32_t dst, const void* src) {
    asm volatile("cp.async.cg.shared.global [%0], [%1], 16;" :: "r"(dst), "l"(src));
}
__device__ __forceinline__ void cp_commit() { asm volatile("cp.async.commit_group;"); }
__device__ __forceinline__ void cp_wait1()  { asm volatile("cp.async.wait_group 1;"); }
__device__ __forceinline__ void cp_wait0()  { asm volatile("cp.async.wait_group 0;"); }

// ----------------------------------------------------------------------------
// Split all 5 inputs fp32 -> (hi, lo) bf16. Dest selected in device code.
// ----------------------------------------------------------------------------
__global__ void split_all(const float* __restrict__ x,
                          const float* __restrict__ Wq,
                          const float* __restrict__ Wk,
                          const float* __restrict__ Wv,
                          const float* __restrict__ Wo)
{
    const float* src;
    bf16 *h, *l;
    int n4;
    switch (blockIdx.y) {
        case 0:  src = x;  h = g_x;  l = g_x  + NX; n4 = NX / 4; break;
        case 1:  src = Wq; h = g_Wq; l = g_Wq + NW; n4 = NW / 4; break;
        case 2:  src = Wk; h = g_Wk; l = g_Wk + NW; n4 = NW / 4; break;
        case 3:  src = Wv; h = g_Wv; l = g_Wv + NW; n4 = NW / 4; break;
        default: src = Wo; h = g_Wo; l = g_Wo + NW; n4 = NW / 4; break;
    }
    int i = blockIdx.x * blockDim.x + threadIdx.x;
    if (i >= n4) return;
    float4 v = ((const float4*)src)[i];
    float vv[4] = {v.x, v.y, v.z, v.w};
    bf16 hh[4], ll[4];
#pragma unroll
    for (int e = 0; e < 4; e++) {
        hh[e] = __float2bfloat16(vv[e]);
        ll[e] = __float2bfloat16(vv[e] - __bfloat162float(hh[e]));
    }
    ((bf162*)h)[i * 2]     = bf162(hh[0], hh[1]);
    ((bf162*)h)[i * 2 + 1] = bf162(hh[2], hh[3]);
    ((bf162*)l)[i * 2]     = bf162(ll[0], ll[1]);
    ((bf162*)l)[i * 2 + 1] = bf162(ll[2], ll[3]);
}

// ----------------------------------------------------------------------------
// RoPE cos/sin table, fp64 angles, one entry per (row, pair).
// ----------------------------------------------------------------------------
__global__ void rope_table_kernel(const int* __restrict__ pos)
{
    int idx = blockIdx.x * blockDim.x + threadIdx.x;
    if (idx >= M_ROWS * HALF_DK) return;
    int i = idx % HALF_DK;
    int m = idx / HALF_DK;
    double ang = (double)pos[m] * pow(10000.0, -(double)i / 64.0);
    g_rope[idx] = make_float2((float)cos(ang), (float)sin(ang));
}

// ----------------------------------------------------------------------------
// Tensor-core GEMM (bf16 hi/lo): C = A * B^T, 3-term split.
// 128x128x32 tiles, 256 threads, 2-stage cp.async (.ca).
// Term order t2,t1,t3: Ah carried t2->t1, Bh carried t1->t3 (12 ldsm/ks).
// MODE: 0 fp32 out; 1 split out; 2 rope+split (K); 3 rope+qscale+split (Q).
// ----------------------------------------------------------------------------
#define BM 128
#define BN 128
#define BKT 32
#define SSTR 40
#define ARR_ELEMS (BM * SSTR)
#define STAGE_ELEMS (4 * ARR_ELEMS)
#define GEMM_SMEM_BYTES (2 * STAGE_ELEMS * 2)   // 81920

template<int MODE, int OFFA, int OFFB>
__device__ __forceinline__
void gemm3_body(const bf16* __restrict__ A, const bf16* __restrict__ B,
                float* __restrict__ C, bf16* __restrict__ Ch,
                int bx, int by)
{
    extern __shared__ bf16 smem[];
    const int tid  = threadIdx.x;
    const int lane = tid & 31;
    const int wid  = tid >> 5;
    const int wm   = (wid >> 2) * 64;
    const int wn   = (wid & 3) * 32;
    const int K = D_MODEL, N = D_MODEL;

    float acc[4][4][4];
#pragma unroll
    for (int mi = 0; mi < 4; mi++)
#pragma unroll
        for (int ni = 0; ni < 4; ni++)
#pragma unroll
            for (int e = 0; e < 4; e++) acc[mi][ni][e] = 0.0f;

    const int lrow = tid >> 1;
    const int lcol = (tid & 1) * 16;
    const bf16* gA = A + (size_t)(by * BM + lrow) * K + lcol;
    const bf16* gB = B + (size_t)(bx * BN + lrow) * K + lcol;

    uint32_t sbase = (uint32_t)__cvta_generic_to_shared(smem);
    uint32_t ldst  = (uint32_t)((lrow * SSTR + lcol) * 2);

    uint32_t aoff[4];
#pragma unroll
    for (int mi = 0; mi < 4; mi++)
        aoff[mi] = (uint32_t)(((wm + mi * 16 + (lane & 15)) * SSTR + (lane >> 4) * 8) * 2);
    uint32_t boff[2];
#pragma unroll
    for (int p = 0; p < 2; p++) {
        int g = lane >> 3;
        boff[p] = (uint32_t)(((wn + p * 16 + (g >> 1) * 8 + (lane & 7)) * SSTR + (g & 1) * 8) * 2);
    }

    const int NT = K / BKT;

    {
        uint32_t so = sbase;
        cp16a(so + ldst,                      gA);
        cp16a(so + ldst + 16,                 gA + 8);
        cp16a(so + ARR_ELEMS * 2 + ldst,      gA + OFFA);
        cp16a(so + ARR_ELEMS * 2 + ldst + 16, gA + OFFA + 8);
        cp16a(so + ARR_ELEMS * 4 + ldst,      gB);
        cp16a(so + ARR_ELEMS * 4 + ldst + 16, gB + 8);
        cp16a(so + ARR_ELEMS * 6 + ldst,      gB + OFFB);
        cp16a(so + ARR_ELEMS * 6 + ldst + 16, gB + OFFB + 8);
        cp_commit();
    }

    for (int kt = 0; kt < NT; kt++) {
        int cur = kt & 1;
        if (kt + 1 < NT) {
            uint32_t so = sbase + (uint32_t)(((kt + 1) & 1) * STAGE_ELEMS * 2);
            int kof = (kt + 1) * BKT;
            cp16a(so + ldst,                      gA + kof);
            cp16a(so + ldst + 16,                 gA + kof + 8);
            cp16a(so + ARR_ELEMS * 2 + ldst,      gA + OFFA + kof);
            cp16a(so + ARR_ELEMS * 2 + ldst + 16, gA + OFFA + kof + 8);
            cp16a(so + ARR_ELEMS * 4 + ldst,      gB + kof);
            cp16a(so + ARR_ELEMS * 4 + ldst + 16, gB + kof + 8);
            cp16a(so + ARR_ELEMS * 6 + ldst,      gB + OFFB + kof);
            cp16a(so + ARR_ELEMS * 6 + ldst + 16, gB + OFFB + kof + 8);
        }
        cp_commit();
        cp_wait1();
        __syncthreads();

        uint32_t sAh = sbase + (uint32_t)(cur * STAGE_ELEMS * 2);
        uint32_t sAl = sAh + ARR_ELEMS * 2;
        uint32_t sBh = sAh + ARR_ELEMS * 4;
        uint32_t sBl = sAh + ARR_ELEMS * 6;

#pragma unroll
        for (int ks = 0; ks < 2; ks++) {
            uint32_t kb = (uint32_t)(ks * 32);
            uint32_t ah[4][4], bb[2][4];

            // t2: Ah * Bl
#pragma unroll
            for (int mi = 0; mi < 4; mi++) ldsm_x4(ah[mi], sAh + aoff[mi] + kb);
#pragma unroll
            for (int p = 0; p < 2; p++)    ldsm_x4(bb[p], sBl + boff[p] + kb);
#pragma unroll
            for (int mi = 0; mi < 4; mi++)
#pragma unroll
                for (int ni = 0; ni < 4; ni++)
                    mma16816(acc[mi][ni], ah[mi], &bb[ni >> 1][(ni & 1) * 2]);

            // t1: Ah * Bh (reuse ah)
#pragma unroll
            for (int p = 0; p < 2; p++)    ldsm_x4(bb[p], sBh + boff[p] + kb);
#pragma unroll
            for (int mi = 0; mi < 4; mi++)
#pragma unroll
                for (int ni = 0; ni < 4; ni++)
                    mma16816(acc[mi][ni], ah[mi], &bb[ni >> 1][(ni & 1) * 2]);

            // t3: Al * Bh (reuse bb)
#pragma unroll
            for (int mi = 0; mi < 4; mi++) ldsm_x4(ah[mi], sAl + aoff[mi] + kb);
#pragma unroll
            for (int mi = 0; mi < 4; mi++)
#pragma unroll
                for (int ni = 0; ni < 4; ni++)
                    mma16816(acc[mi][ni], ah[mi], &bb[ni >> 1][(ni & 1) * 2]);
        }
        __syncthreads();
    }

    const float qscale = 0.08838834764831845f;   // 1/sqrt(128)
#pragma unroll
    for (int mi = 0; mi < 4; mi++) {
        int r0 = by * BM + wm + mi * 16 + (lane >> 2);
#pragma unroll
        for (int ni = 0; ni < 4; ni++) {
            int cc = bx * BN + wn + ni * 8 + (lane & 3) * 2;
            float v0 = acc[mi][ni][0], v1 = acc[mi][ni][1];   // row r0,  cols cc,cc+1
            float v2 = acc[mi][ni][2], v3 = acc[mi][ni][3];   // row r0+8
            if (MODE >= 2) {
                int i = (cc & 127) >> 1;                      // rope pair within head
                float2 cs0 = g_rope[r0 * HALF_DK + i];
                float r1 = v0 * cs0.x - v1 * cs0.y;
                float r2 = v0 * cs0.y + v1 * cs0.x;
                v0 = r1; v1 = r2;
                float2 cs1 = g_rope[(r0 + 8) * HALF_DK + i];
                float r3 = v2 * cs1.x - v3 * cs1.y;
                float r4 = v2 * cs1.y + v3 * cs1.x;
                v2 = r3; v3 = r4;
                if (MODE == 3) { v0 *= qscale; v1 *= qscale; v2 *= qscale; v3 *= qscale; }
            }
            if (MODE >= 1) {
                bf16* Cl = Ch + NX;
                bf162 h0 = __floats2bfloat162_rn(v0, v1);
                bf162 l0 = __floats2bfloat162_rn(v0 - __bfloat162float(h0.x),
                                                 v1 - __bfloat162float(h0.y));
                *(bf162*)&Ch[(size_t)r0 * N + cc] = h0;
                *(bf162*)&Cl[(size_t)r0 * N + cc] = l0;
                bf162 h1 = __floats2bfloat162_rn(v2, v3);
                bf162 l1 = __floats2bfloat162_rn(v2 - __bfloat162float(h1.x),
                                                 v3 - __bfloat162float(h1.y));
                *(bf162*)&Ch[(size_t)(r0 + 8) * N + cc] = h1;
                *(bf162*)&Cl[(size_t)(r0 + 8) * N + cc] = l1;
            } else {
                *(float2*)&C[(size_t)r0 * N + cc]       = make_float2(v0, v1);
                *(float2*)&C[(size_t)(r0 + 8) * N + cc] = make_float2(v2, v3);
            }
        }
    }
}

__global__ __launch_bounds__(256, 2)
void qkv_tc()
{
    if (blockIdx.z == 0)
        gemm3_body<3, NX, NW>(g_x, g_Wq, nullptr, g_Q, blockIdx.x, blockIdx.y);
    else if (blockIdx.z == 1)
        gemm3_body<2, NX, NW>(g_x, g_Wk, nullptr, g_K, blockIdx.x, blockIdx.y);
    else
        gemm3_body<1, NX, NW>(g_x, g_Wv, nullptr, g_V, blockIdx.x, blockIdx.y);
}

__global__ __launch_bounds__(256, 2)
void out_tc(float* __restrict__ out)
{
    gemm3_body<0, NX, NW>(g_ctx, g_Wo, out, nullptr, blockIdx.x, blockIdx.y);
}

// ----------------------------------------------------------------------------
// Tensor-core flash attention (R13 best, unchanged). Br=128, Bc=64,
// 256 threads, 2-stage cp.async (.cg) KV pipeline, Q fragments hoisted.
// ----------------------------------------------------------------------------
#define ASTR 136
#define SQL_OFF (128 * ASTR)
#define SKV0 (2 * 128 * ASTR)
#define KV_STAGE (4 * 64 * ASTR)
#define ATTN_SMEM_BYTES ((SKV0 + 2 * KV_STAGE) * 2)

__global__ __launch_bounds__(256, 1)
void attn_tc()
{
    extern __shared__ bf16 sm[];
    const int tid  = threadIdx.x;
    const int lane = tid & 31;
    const int w    = tid >> 5;
    const int qt   = (int)gridDim.x - 1 - (int)blockIdx.x;
    const int bh   = blockIdx.y;
    const int b    = bh >> 4;
    const int h    = bh & 15;
    const int qrow0 = qt * 128;
    const int wrow  = w * 16;

    uint32_t sbase = (uint32_t)__cvta_generic_to_shared(sm);

    const int kvrow  = tid >> 2;
    const int kvcolb = (tid & 3) * 32;
    const size_t kvg = (size_t)(b * SEQ + kvrow) * D_MODEL + h * D_K + kvcolb;
    const uint32_t kvs = (uint32_t)((kvrow * ASTR + kvcolb) * 2);

    // ---- Q tile (hi/lo) -> smem ----
    {
        int row = tid >> 1, colb = (tid & 1) * 64;
        size_t gq = (size_t)(b * SEQ + qrow0 + row) * D_MODEL + h * D_K + colb;
        uint32_t sq = sbase + (uint32_t)((row * ASTR + colb) * 2);
#pragma unroll
        for (int cc = 0; cc < 8; cc++) {
            cp16g(sq + cc * 16,               g_Q + gq + cc * 8);
            cp16g(sq + SQL_OFF * 2 + cc * 16, g_Q + NX + gq + cc * 8);
        }
    }

    const int njt = 2 * qt + 2;

    // ---- KV tile 0 -> stage 0 ----
    {
        uint32_t sb = sbase + (uint32_t)(SKV0 * 2) + kvs;
#pragma unroll
        for (int cc = 0; cc < 4; cc++) {
            cp16g(sb + cc * 16,                     g_K + kvg + cc * 8);
            cp16g(sb + 64 * ASTR * 2 + cc * 16,     g_K + NX + kvg + cc * 8);
            cp16g(sb + 2 * 64 * ASTR * 2 + cc * 16, g_V + kvg + cc * 8);
            cp16g(sb + 3 * 64 * ASTR * 2 + cc * 16, g_V + NX + kvg + cc * 8);
        }
        cp_commit();
    }

    // ---- hoist Q fragments into registers (loop-invariant) ----
    uint32_t aoff = (uint32_t)(((wrow + (lane & 15)) * ASTR + (lane >> 4) * 8) * 2);
    cp_wait0();
    __syncthreads();
    uint32_t qh[8][4], ql[8][4];
#pragma unroll
    for (int ks = 0; ks < 8; ks++) {
        ldsm_x4(qh[ks], sbase + aoff + (uint32_t)(ks * 32));
        ldsm_x4(ql[ks], sbase + SQL_OFF * 2 + aoff + (uint32_t)(ks * 32));
    }

    float O[16][4];
#pragma unroll
    for (int nt = 0; nt < 16; nt++)
#pragma unroll
        for (int e = 0; e < 4; e++) O[nt][e] = 0.0f;
    float m_i[2] = {-1e30f, -1e30f};
    float l_i[2] = {0.0f, 0.0f};

    uint32_t boff[4];
#pragma unroll
    for (int p = 0; p < 4; p++) {
        int g = lane >> 3;
        boff[p] = (uint32_t)(((p * 16 + (g >> 1) * 8 + (lane & 7)) * ASTR + (g & 1) * 8) * 2);
    }
    int vrow = ((lane >> 3) & 1) * 8 + (lane & 7);
    int vcol = (lane >> 4) * 8;

    for (int j = 0; j < njt; j++) {
        int s = j & 1;
        if (j + 1 < njt) {
            uint32_t sb = sbase + (uint32_t)((SKV0 + (s ^ 1) * KV_STAGE) * 2) + kvs;
            size_t gb = kvg + (size_t)(j + 1) * 64 * D_MODEL;
#pragma unroll
            for (int cc = 0; cc < 4; cc++) {
                cp16g(sb + cc * 16,                     g_K + gb + cc * 8);
                cp16g(sb + 64 * ASTR * 2 + cc * 16,     g_K + NX + gb + cc * 8);
                cp16g(sb + 2 * 64 * ASTR * 2 + cc * 16, g_V + gb + cc * 8);
                cp16g(sb + 3 * 64 * ASTR * 2 + cc * 16, g_V + NX + gb + cc * 8);
            }
        }
        cp_commit();
        cp_wait1();
        __syncthreads();

        uint32_t skh = sbase + (uint32_t)((SKV0 + s * KV_STAGE) * 2);
        uint32_t skl = skh + 64 * ASTR * 2;
        uint32_t svh = skh + 2 * 64 * ASTR * 2;
        uint32_t svl = skh + 3 * 64 * ASTR * 2;

        bool active = (j * 64 <= qrow0 + wrow + 15);
        if (active) {
            float S[8][4];
#pragma unroll
            for (int t = 0; t < 8; t++)
#pragma unroll
                for (int e = 0; e < 4; e++) S[t][e] = 0.0f;

#pragma unroll
            for (int ks = 0; ks < 8; ks++) {
                uint32_t kb = (uint32_t)(ks * 32);
                uint32_t bb[4][4];
#pragma unroll
                for (int p = 0; p < 4; p++) ldsm_x4(bb[p], skl + boff[p] + kb);
#pragma unroll
                for (int t = 0; t < 8; t++) mma16816(S[t], qh[ks], &bb[t >> 1][(t & 1) * 2]);
#pragma unroll
                for (int p = 0; p < 4; p++) ldsm_x4(bb[p], skh + boff[p] + kb);
#pragma unroll
                for (int t = 0; t < 8; t++) mma16816(S[t], qh[ks], &bb[t >> 1][(t & 1) * 2]);
#pragma unroll
                for (int t = 0; t < 8; t++) mma16816(S[t], ql[ks], &bb[t >> 1][(t & 1) * 2]);
            }

            int grow0 = qrow0 + wrow + (lane >> 2);
            int grow1 = grow0 + 8;
            if (j * 64 + 63 > qrow0 + wrow) {
#pragma unroll
                for (int t = 0; t < 8; t++) {
                    int c0 = j * 64 + t * 8 + 2 * (lane & 3);
                    if (c0     > grow0) S[t][0] = -1e30f;
                    if (c0 + 1 > grow0) S[t][1] = -1e30f;
                    if (c0     > grow1) S[t][2] = -1e30f;
                    if (c0 + 1 > grow1) S[t][3] = -1e30f;
                }
            }

            float mx0 = -1e30f, mx1 = -1e30f;
#pragma unroll
            for (int t = 0; t < 8; t++) {
                mx0 = fmaxf(mx0, fmaxf(S[t][0], S[t][1]));
                mx1 = fmaxf(mx1, fmaxf(S[t][2], S[t][3]));
            }
            mx0 = fmaxf(mx0, __shfl_xor_sync(0xffffffffu, mx0, 1));
            mx0 = fmaxf(mx0, __shfl_xor_sync(0xffffffffu, mx0, 2));
            mx1 = fmaxf(mx1, __shfl_xor_sync(0xffffffffu, mx1, 1));
            mx1 = fmaxf(mx1, __shfl_xor_sync(0xffffffffu, mx1, 2));

            float mn0 = fmaxf(m_i[0], mx0), mn1 = fmaxf(m_i[1], mx1);
            float al0 = __expf(m_i[0] - mn0), al1 = __expf(m_i[1] - mn1);
            m_i[0] = mn0; m_i[1] = mn1;

            float sum0 = 0.0f, sum1 = 0.0f;
#pragma unroll
            for (int t = 0; t < 8; t++) {
                S[t][0] = __expf(S[t][0] - mn0);
                S[t][1] = __expf(S[t][1] - mn0);
                S[t][2] = __expf(S[t][2] - mn1);
                S[t][3] = __expf(S[t][3] - mn1);
                sum0 += S[t][0] + S[t][1];
                sum1 += S[t][2] + S[t][3];
            }
            sum0 += __shfl_xor_sync(0xffffffffu, sum0, 1);
            sum0 += __shfl_xor_sync(0xffffffffu, sum0, 2);
            sum1 += __shfl_xor_sync(0xffffffffu, sum1, 1);
            sum1 += __shfl_xor_sync(0xffffffffu, sum1, 2);
            l_i[0] = l_i[0] * al0 + sum0;
            l_i[1] = l_i[1] * al1 + sum1;

#pragma unroll
            for (int nt = 0; nt < 16; nt++) {
                O[nt][0] *= al0; O[nt][1] *= al0;
                O[nt][2] *= al1; O[nt][3] *= al1;
            }

#pragma unroll
            for (int kb = 0; kb < 4; kb++) {
                uint32_t ph[4], pl[4];
#pragma unroll
                for (int u = 0; u < 2; u++) {
                    int t = 2 * kb + u;
                    bf162 h01 = __floats2bfloat162_rn(S[t][0], S[t][1]);
                    bf162 l01 = __floats2bfloat162_rn(S[t][0] - __bfloat162float(h01.x),
                                                      S[t][1] - __bfloat162float(h01.y));
                    bf162 h23 = __floats2bfloat162_rn(S[t][2], S[t][3]);
                    bf162 l23 = __floats2bfloat162_rn(S[t][2] - __bfloat162float(h23.x),
                                                      S[t][3] - __bfloat162float(h23.y));
                    ph[2 * u]     = *(uint32_t*)&h01;
                    pl[2 * u]     = *(uint32_t*)&l01;
                    ph[2 * u + 1] = *(uint32_t*)&h23;
                    pl[2 * u + 1] = *(uint32_t*)&l23;
                }
#pragma unroll
                for (int half = 0; half < 2; half++) {
                    uint32_t vb[4][4];
#pragma unroll
                    for (int i = 0; i < 4; i++)
                        ldsm_x4_t(vb[i], svh + (uint32_t)(((kb * 16 + vrow) * ASTR +
                                                (half * 4 + i) * 16 + vcol) * 2));
#pragma unroll
                    for (int nt = 0; nt < 8; nt++)
                        mma16816(O[half * 8 + nt], ph, &vb[nt >> 1][(nt & 1) * 2]);
#pragma unroll
                    for (int nt = 0; nt < 8; nt++)
                        mma16816(O[half * 8 + nt], pl, &vb[nt >> 1][(nt & 1) * 2]);
#pragma unroll
                    for (int i = 0; i < 4; i++)
                        ldsm_x4_t(vb[i], svl + (uint32_t)(((kb * 16 + vrow) * ASTR +
                                                (half * 4 + i) * 16 + vcol) * 2));
#pragma unroll
                    for (int nt = 0; nt < 8; nt++)
                        mma16816(O[half * 8 + nt], ph, &vb[nt >> 1][(nt & 1) * 2]);
                }
            }
        }
        __syncthreads();
    }

    float inv0 = 1.0f / l_i[0], inv1 = 1.0f / l_i[1];
    size_t gr0 = (size_t)(b * SEQ + qrow0 + wrow + (lane >> 2)) * D_MODEL + h * D_K;
    size_t gr1 = gr0 + (size_t)8 * D_MODEL;
#pragma unroll
    for (int nt = 0; nt < 16; nt++) {
        int d0 = nt * 8 + (lane & 3) * 2;
        float v0 = O[nt][0] * inv0, v1 = O[nt][1] * inv0;
        bf162 h0 = __floats2bfloat162_rn(v0, v1);
        bf162 l0 = __floats2bfloat162_rn(v0 - __bfloat162float(h0.x),
                                         v1 - __bfloat162float(h0.y));
        *(bf162*)&g_ctx[gr0 + d0]      = h0;
        *(bf162*)&g_ctx[NX + gr0 + d0] = l0;
        float v2 = O[nt][2] * inv1, v3 = O[nt][3] * inv1;
        bf162 h1 = __floats2bfloat162_rn(v2, v3);
        bf162 l1 = __floats2bfloat162_rn(v2 - __bfloat162float(h1.x),
                                         v3 - __bfloat162float(h1.y));
        *(bf162*)&g_ctx[gr1 + d0]      = h1;
        *(bf162*)&g_ctx[NX + gr1 + d0] = l1;
    }
}

// ----------------------------------------------------------------------------
// Launcher
// ----------------------------------------------------------------------------
extern "C" void kernel_launch(void* const* d_in, const int* in_sizes, int n_in,
                              void* d_out, int out_size)
{
    const float* x   = (const float*)d_in[0];
    const int*   pos = (const int*)d_in[1];
    const float* Wq  = (const float*)d_in[2];
    const float* Wk  = (const float*)d_in[3];
    const float* Wv  = (const float*)d_in[4];
    const float* Wo  = (const float*)d_in[5];
    float* out = (float*)d_out;

    {
        int nb = (NX / 4 + 255) / 256;
        split_all<<<dim3(nb, 5), 256>>>(x, Wq, Wk, Wv, Wo);
    }
    {
        int total = M_ROWS * HALF_DK;
        rope_table_kernel<<<(total + 255) / 256, 256>>>(pos);
    }

    cudaFuncSetAttribute(qkv_tc, cudaFuncAttributeMaxDynamicSharedMemorySize,
                         GEMM_SMEM_BYTES);
    cudaFuncSetAttribute(out_tc, cudaFuncAttributeMaxDynamicSharedMemorySize,
                         GEMM_SMEM_BYTES);
    cudaFuncSetAttribute(attn_tc, cudaFuncAttributeMaxDynamicSharedMemorySize,
                         ATTN_SMEM_BYTES);

    dim3 gthr(256);
    qkv_tc<<<dim3(D_MODEL / BN, M_ROWS / BM, 3), gthr, GEMM_SMEM_BYTES>>>();

    attn_tc<<<dim3(SEQ / 128, BATCH * NUM_HEADS), gthr, ATTN_SMEM_BYTES>>>();

    out_tc<<<dim3(D_MODEL / BN, M_ROWS / BM), gthr, GEMM_SMEM_BYTES>>>(out);
}